// round 3
// baseline (speedup 1.0000x reference)
#include <cuda_runtime.h>

// Spline1DInterpolant: out[q] = sum_i c[i] * u(|s_q + 2 - (i+1)|),
// s = (x - a)/h, h = (b - a)/n. Cubic B-spline, support t < 2 => exactly 4
// consecutive taps per query: i = floor(s) .. floor(s)+3.
//
// Latency-bound. Key trick: the c-gather depends on x, so cold it's two serial
// DRAM round trips. c is only 16KB -> prefetch all of it into L2 (non-blocking,
// independent of x) at kernel entry; the dependent gathers then hit L2.

__device__ __forceinline__ float bspline_basis(float t) {
    // t in [0,2]; inner (t<=1): 4 - 6t^2 + 3t^3 ; outer: (2-t)^3
    float t2 = t * t;
    float inner = 4.0f - 6.0f * t2 + 3.0f * t2 * t;
    float om = 2.0f - t;
    float outer = om * om * om;
    return (t <= 1.0f) ? inner : outer;
}

__global__ void __launch_bounds__(128)
spline1d_kernel(const float* __restrict__ x,
                const float* __restrict__ a,
                const float* __restrict__ b,
                const float* __restrict__ n,
                const float* __restrict__ c,
                float* __restrict__ out,
                int nb, int nc) {
    int tid = blockIdx.x * 128 + threadIdx.x;

    // Non-blocking L2 prefetch of c, issued BEFORE anything depends on x.
    // 128 blocks x 1 line (32 floats) covers nc=4096 exactly; guard for safety.
    {
        int line = blockIdx.x * 32;           // float index of a 128B line
        if (threadIdx.x == 0 && line < nc) {
            asm volatile("prefetch.global.L2 [%0];" :: "l"(c + line));
        }
    }

    if (tid >= nb) return;

    // Reference-exact arithmetic (fp32, true division).
    float xq = __ldg(x + tid);
    float a0 = __ldg(a);
    float h  = (__ldg(b) - a0) / __ldg(n);
    float s  = (xq - a0) / h;

    int i0 = (int)floorf(s);

    float sum = 0.0f;
#pragma unroll
    for (int k = 0; k < 4; k++) {
        int i = i0 + k;
        float t = fabsf(s + 2.0f - (float)(i + 1));   // same cancellation as ref
        float u = bspline_basis(t);
        if ((unsigned)i < (unsigned)nc) {
            sum = fmaf(__ldg(c + i), u, sum);
        }
    }
    out[tid] = sum;
}

extern "C" void kernel_launch(void* const* d_in, const int* in_sizes, int n_in,
                              void* d_out, int out_size) {
    const float* x = (const float*)d_in[0];   // [B,1] fp32
    const float* a = (const float*)d_in[1];   // [1]
    const float* b = (const float*)d_in[2];   // [1]
    const float* n = (const float*)d_in[3];   // [1]
    const float* c = (const float*)d_in[4];   // [C]
    float* out = (float*)d_out;

    int nb = in_sizes[0];      // 16384
    int nc = in_sizes[4];      // 4096

    int blocks = (nb + 127) / 128;            // 128 blocks, one wave
    spline1d_kernel<<<blocks, 128>>>(x, a, b, n, c, out, nb, nc);
}

// round 4
// speedup vs baseline: 1.0505x; 1.0505x over previous
#include <cuda_runtime.h>

// Spline1DInterpolant: out[q] = sum_i c[i] * u(|s_q + 2 - (i+1)|),
// s = (x - a)/h, h = (b - a)/n. Cubic B-spline, support t < 2 => exactly 4
// consecutive taps: i = floor(s) .. floor(s)+3.
//
// Latency-bound. Warm-path chain was LDG x (L2) -> div -> gather c (L2): two
// serial L2 round trips (L1 is flushed every launch on sm_103a). Stage all of
// c (16KB) into smem with loads INDEPENDENT of x so the two memory latencies
// overlap; the dependent taps become 29-cyc LDS instead of 250-cyc L2 hits.

static constexpr int MAX_C = 4096;

__device__ __forceinline__ float bspline_basis(float t) {
    // t in [0,2]; inner (t<=1): 4 - 6t^2 + 3t^3 ; outer: (2-t)^3
    float t2 = t * t;
    float inner = 4.0f - 6.0f * t2 + 3.0f * t2 * t;
    float om = 2.0f - t;
    float outer = om * om * om;
    return (t <= 1.0f) ? inner : outer;
}

__global__ void __launch_bounds__(128)
spline1d_smem(const float* __restrict__ x,
              const float* __restrict__ a,
              const float* __restrict__ b,
              const float* __restrict__ n,
              const float* __restrict__ c,
              float* __restrict__ out,
              int nb, int nc) {
    __shared__ float cs[MAX_C];

    int tid = blockIdx.x * 128 + threadIdx.x;

    // Issue ALL independent loads up front: x + scalars + bulk c -> smem.
    float xq = (tid < nb) ? __ldg(x + tid) : 0.0f;
    float a0 = __ldg(a);
    float bv = __ldg(b);
    float nv = __ldg(n);

    {
        const float4* c4 = (const float4*)c;
        float4* cs4 = (float4*)cs;
        int nvec = nc >> 2;                       // 1024 for nc=4096
#pragma unroll 8
        for (int i = threadIdx.x; i < nvec; i += 128)
            cs4[i] = __ldg(c4 + i);
        // scalar remainder (never taken for nc=4096)
        for (int i = (nvec << 2) + threadIdx.x; i < nc; i += 128)
            cs[i] = __ldg(c + i);
    }
    __syncthreads();

    if (tid >= nb) return;

    // Reference-exact arithmetic (fp32, true division).
    float h = (bv - a0) / nv;
    float s = (xq - a0) / h;
    int i0 = (int)floorf(s);

    float sum = 0.0f;
#pragma unroll
    for (int k = 0; k < 4; k++) {
        int i = i0 + k;
        float t = fabsf(s + 2.0f - (float)(i + 1));   // same cancellation as ref
        float u = bspline_basis(t);
        if ((unsigned)i < (unsigned)nc) {
            sum = fmaf(cs[i], u, sum);
        }
    }
    out[tid] = sum;
}

// Fallback for nc > MAX_C (not hit for this problem's fixed shapes).
__global__ void __launch_bounds__(128)
spline1d_global(const float* __restrict__ x,
                const float* __restrict__ a,
                const float* __restrict__ b,
                const float* __restrict__ n,
                const float* __restrict__ c,
                float* __restrict__ out,
                int nb, int nc) {
    int tid = blockIdx.x * 128 + threadIdx.x;
    if (tid >= nb) return;
    float a0 = __ldg(a);
    float h  = (__ldg(b) - a0) / __ldg(n);
    float s  = (__ldg(x + tid) - a0) / h;
    int i0 = (int)floorf(s);
    float sum = 0.0f;
#pragma unroll
    for (int k = 0; k < 4; k++) {
        int i = i0 + k;
        float t = fabsf(s + 2.0f - (float)(i + 1));
        float u = bspline_basis(t);
        if ((unsigned)i < (unsigned)nc)
            sum = fmaf(__ldg(c + i), u, sum);
    }
    out[tid] = sum;
}

extern "C" void kernel_launch(void* const* d_in, const int* in_sizes, int n_in,
                              void* d_out, int out_size) {
    const float* x = (const float*)d_in[0];   // [B,1] fp32
    const float* a = (const float*)d_in[1];   // [1]
    const float* b = (const float*)d_in[2];   // [1]
    const float* n = (const float*)d_in[3];   // [1]
    const float* c = (const float*)d_in[4];   // [C]
    float* out = (float*)d_out;

    int nb = in_sizes[0];      // 16384
    int nc = in_sizes[4];      // 4096

    int blocks = (nb + 127) / 128;            // 128 blocks, one wave
    if (nc <= MAX_C) {
        spline1d_smem<<<blocks, 128>>>(x, a, b, n, c, out, nb, nc);
    } else {
        spline1d_global<<<blocks, 128>>>(x, a, b, n, c, out, nb, nc);
    }
}